// round 17
// baseline (speedup 1.0000x reference)
#include <cuda_runtime.h>

#define N_NODES 100000
#define N_EDGES 1200000
#define D_FEAT  64
#define D_OUT   128
#define SCAN_CHUNK  1024
#define SCAN_BLOCKS ((N_NODES + SCAN_CHUNK - 1) / SCAN_CHUNK)   // 98
#define W_STRIDE 136
#define S_STRIDE 68
#define SMEM_FLOATS (64 * W_STRIDE + 8 * 16 * S_STRIDE)
#define SMEM_BYTES (SMEM_FLOATS * 4)                       // 69632

// Scratch (no allocs allowed)
__device__ int g_esrc[N_EDGES];
__device__ int g_rank[N_EDGES];
__device__ int g_count[N_NODES];
__device__ int g_off[N_NODES + 1];
__device__ int g_bsum[SCAN_BLOCKS];
__device__ int g_bscan[SCAN_BLOCKS];
__device__ int g_arrive;
__device__ int g_release;
__device__ float g_Wt[64 * W_STRIDE];

// ---------------------------------------------------------------------------
// K0: zero counters, reset scan flags, build tf32 Wt.
// ---------------------------------------------------------------------------
__global__ void __launch_bounds__(256) init_kernel(const float* __restrict__ W) {
    int i = blockIdx.x * 256 + threadIdx.x;
    if (i < N_NODES) g_count[i] = 0;
    if (i == 0) { g_arrive = 0; g_release = 0; }
    if (i < 64 * W_STRIDE) {
        int k = i / W_STRIDE, n = i % W_STRIDE;
        float v = (n < D_OUT) ? __ldg(&W[n * D_FEAT + k]) : 0.f;
        unsigned t;
        asm("cvt.rna.tf32.f32 %0, %1;" : "=r"(t) : "f"(v));
        g_Wt[i] = __uint_as_float(t);
    }
}

// ---------------------------------------------------------------------------
// K1: count+rank, 4 edges/thread.
// ---------------------------------------------------------------------------
__global__ void __launch_bounds__(256) count_kernel(const int* __restrict__ dst) {
    int q = blockIdx.x * 256 + threadIdx.x;
    if (q * 4 >= N_EDGES) return;
    int4 d4 = __ldg((const int4*)dst + q);
    int4 r4;
    r4.x = ((unsigned)d4.x < N_NODES) ? atomicAdd(&g_count[d4.x], 1) : 0;
    r4.y = ((unsigned)d4.y < N_NODES) ? atomicAdd(&g_count[d4.y], 1) : 0;
    r4.z = ((unsigned)d4.z < N_NODES) ? atomicAdd(&g_count[d4.z], 1) : 0;
    r4.w = ((unsigned)d4.w < N_NODES) ? atomicAdd(&g_count[d4.w], 1) : 0;
    ((int4*)g_rank)[q] = r4;
}

// ---------------------------------------------------------------------------
// K2: single-kernel two-level exclusive scan.
// ---------------------------------------------------------------------------
__global__ void __launch_bounds__(256) scan_fused_kernel() {
    __shared__ int sh[256];
    __shared__ int sp[128];
    __shared__ int s_last;
    int b = blockIdx.x, tid = threadIdx.x;
    int base = b * SCAN_CHUNK + tid * 4;

    int c[4]; int s = 0;
    #pragma unroll
    for (int j = 0; j < 4; j++) {
        int i = base + j;
        c[j] = (i < N_NODES) ? g_count[i] : 0;
        s += c[j];
    }
    sh[tid] = s; __syncthreads();
    for (int o = 128; o; o >>= 1) { if (tid < o) sh[tid] += sh[tid + o]; __syncthreads(); }
    if (tid == 0) {
        g_bsum[b] = sh[0];
        __threadfence();
        s_last = (atomicAdd(&g_arrive, 1) == SCAN_BLOCKS - 1);
    }
    __syncthreads();

    if (s_last) {
        int v = (tid < SCAN_BLOCKS) ? g_bsum[tid] : 0;
        if (tid < 128) sp[tid] = v;
        __syncthreads();
        #pragma unroll
        for (int o = 1; o < 128; o <<= 1) {
            int t = (tid < 128 && tid >= o) ? sp[tid - o] : 0;
            __syncthreads();
            if (tid < 128) sp[tid] += t;
            __syncthreads();
        }
        if (tid < SCAN_BLOCKS) g_bscan[tid] = sp[tid] - v;
        if (tid == 127) g_off[N_NODES] = sp[127];
        __threadfence();
        __syncthreads();
        if (tid == 0) atomicExch(&g_release, 1);
    }

    if (tid == 0) while (atomicAdd(&g_release, 0) == 0) {}
    __syncthreads();

    sh[tid] = s; __syncthreads();
    int v2 = s;
    #pragma unroll
    for (int o = 1; o < 256; o <<= 1) {
        int t = (tid >= o) ? sh[tid - o] : 0;
        __syncthreads();
        sh[tid] += t;
        __syncthreads();
    }
    int run = g_bscan[b] + (sh[tid] - v2);
    #pragma unroll
    for (int j = 0; j < 4; j++) {
        int i = base + j;
        if (i < N_NODES) { g_off[i] = run; run += c[j]; }
    }
}

// ---------------------------------------------------------------------------
// K3: bin, 4 edges/thread — atomic-free.
// ---------------------------------------------------------------------------
__global__ void __launch_bounds__(256) bin_kernel(
    const int* __restrict__ src, const int* __restrict__ dst)
{
    int q = blockIdx.x * 256 + threadIdx.x;
    if (q * 4 >= N_EDGES) return;
    int4 d4 = __ldg((const int4*)dst + q);
    int4 r4 = __ldg((const int4*)g_rank + q);
    int4 s4 = __ldg((const int4*)src + q);
    if ((unsigned)d4.x < N_NODES) g_esrc[__ldg(&g_off[d4.x]) + r4.x] = s4.x;
    if ((unsigned)d4.y < N_NODES) g_esrc[__ldg(&g_off[d4.y]) + r4.y] = s4.y;
    if ((unsigned)d4.z < N_NODES) g_esrc[__ldg(&g_off[d4.z]) + r4.z] = s4.z;
    if ((unsigned)d4.w < N_NODES) g_esrc[__ldg(&g_off[d4.w]) + r4.w] = s4.w;
}

// ---------------------------------------------------------------------------
// K4: attention + tensor-core FC, with CROSS-QUAD row prefetch.
// Model recalibration (R9/R15/R16 all ~neutral): the binder is the per-quad
// L2 round-trip — quad q+1's row loads were issued only after quad q's
// accumulate, exposing ~250-380 cyc per 4 edges.  Fix: double-buffered row
// registers; while computing quad q, quad q+1's rows (or the NEXT NODE's
// quad-0 rows, whose srcids R16's front-pipeline already fetched) are in
// flight.  Exposed latency/quad: ~250 -> ~50 cyc.
// ---------------------------------------------------------------------------
__device__ __forceinline__ float dot4(const float4 a, const float4 u) {
    return fmaf(a.x, u.x, fmaf(a.y, u.y, fmaf(a.z, u.z, a.w * u.w)));
}

__device__ __forceinline__ unsigned to_tf32(float x) {
    unsigned t;
    asm("cvt.rna.tf32.f32 %0, %1;" : "=r"(t) : "f"(x));
    return t;
}

// non-prefetched fallback for deg>16 spillover blocks (rare)
__device__ __forceinline__ void process16(
    unsigned hm, int hl, const float4* __restrict__ hk4,
    const float4 u, int srcid, int n, float4& acc, float& denom)
{
    for (int k0 = 0; k0 < n; k0 += 4) {
        int s0 = __shfl_sync(hm, srcid, min(k0 + 0, 15), 16);
        int s1 = __shfl_sync(hm, srcid, min(k0 + 1, 15), 16);
        int s2 = __shfl_sync(hm, srcid, min(k0 + 2, 15), 16);
        int s3 = __shfl_sync(hm, srcid, min(k0 + 3, 15), 16);
        float4 a0 = make_float4(0.f, 0.f, 0.f, 0.f);
        float4 a1 = a0, a2 = a0, a3 = a0;
        a0 = __ldg(hk4 + (size_t)s0 * 16 + hl);
        if (k0 + 1 < n) a1 = __ldg(hk4 + (size_t)s1 * 16 + hl);
        if (k0 + 2 < n) a2 = __ldg(hk4 + (size_t)s2 * 16 + hl);
        if (k0 + 3 < n) a3 = __ldg(hk4 + (size_t)s3 * 16 + hl);
        float p0 = dot4(a0, u), p1 = dot4(a1, u);
        float p2 = dot4(a2, u), p3 = dot4(a3, u);
        #pragma unroll
        for (int o = 8; o; o >>= 1) {
            p0 += __shfl_xor_sync(hm, p0, o, 16);
            p1 += __shfl_xor_sync(hm, p1, o, 16);
            p2 += __shfl_xor_sync(hm, p2, o, 16);
            p3 += __shfl_xor_sync(hm, p3, o, 16);
        }
        { float e = __expf(p0);
          acc.x = fmaf(e, a0.x, acc.x); acc.y = fmaf(e, a0.y, acc.y);
          acc.z = fmaf(e, a0.z, acc.z); acc.w = fmaf(e, a0.w, acc.w); denom += e; }
        if (k0 + 1 < n) { float e = __expf(p1);
          acc.x = fmaf(e, a1.x, acc.x); acc.y = fmaf(e, a1.y, acc.y);
          acc.z = fmaf(e, a1.z, acc.z); acc.w = fmaf(e, a1.w, acc.w); denom += e; }
        if (k0 + 2 < n) { float e = __expf(p2);
          acc.x = fmaf(e, a2.x, acc.x); acc.y = fmaf(e, a2.y, acc.y);
          acc.z = fmaf(e, a2.z, acc.z); acc.w = fmaf(e, a2.w, acc.w); denom += e; }
        if (k0 + 3 < n) { float e = __expf(p3);
          acc.x = fmaf(e, a3.x, acc.x); acc.y = fmaf(e, a3.y, acc.y);
          acc.z = fmaf(e, a3.z, acc.z); acc.w = fmaf(e, a3.w, acc.w); denom += e; }
    }
}

extern __shared__ float sh[];   // [0,8704): Wt_s  [8704,17408): staging

__global__ void __launch_bounds__(256) attn_fc_kernel(
    const float* __restrict__ hk, const float* __restrict__ hu,
    const float* __restrict__ b, float* __restrict__ out)
{
    float* Wt_s = sh;
    int tid = threadIdx.x;
    for (int i = tid; i < 64 * W_STRIDE; i += 256)
        Wt_s[i] = g_Wt[i];
    __syncthreads();

    int wid = tid >> 5, lane = tid & 31;
    int half = lane >> 4, hl = lane & 15;
    unsigned hm = half ? 0xFFFF0000u : 0x0000FFFFu;
    float* stage = sh + 64 * W_STRIDE + wid * 16 * S_STRIDE;
    const float4* hk4 = (const float4*)hk;
    const float4* hu4 = (const float4*)hu;

    int nbase = (blockIdx.x * 8 + wid) * 16;
    int hbase = nbase + half * 8;

    // ---- cross-node front: all 8 bounds in one coalesced LDG ----
    int offv = __ldg(&g_off[min(hbase + hl, N_NODES)]);
    int beg = __shfl_sync(hm, offv, 0, 16);
    int end = __shfl_sync(hm, offv, 1, 16);
    int n   = min(16, end - beg);                        // next-node state
    float4 u = __ldg(hu4 + (size_t)min(hbase, N_NODES - 1) * 16 + hl);
    int srcid = (hl < n) ? __ldg(&g_esrc[beg + hl]) : 0;
    float4 pr0 = make_float4(0.f, 0.f, 0.f, 0.f);
    float4 pr1 = pr0, pr2 = pr0, pr3 = pr0;              // prefetched rows
    {
        int s0 = __shfl_sync(hm, srcid, 0, 16);
        int s1 = __shfl_sync(hm, srcid, 1, 16);
        int s2 = __shfl_sync(hm, srcid, 2, 16);
        int s3 = __shfl_sync(hm, srcid, 3, 16);
        if (0 < n) pr0 = __ldg(hk4 + (size_t)s0 * 16 + hl);
        if (1 < n) pr1 = __ldg(hk4 + (size_t)s1 * 16 + hl);
        if (2 < n) pr2 = __ldg(hk4 + (size_t)s2 * 16 + hl);
        if (3 < n) pr3 = __ldg(hk4 + (size_t)s3 * 16 + hl);
    }

    for (int m = 0; m < 8; m++) {
        int node = hbase + m;
        if (node >= N_NODES) break;                      // half-uniform
        // snapshot current node state
        float4 cu = u;
        int csrc = srcid, cn = n, cbeg = beg, cend = end;

        // prefetch NEXT node's front (bounds/u/srcid)
        if (m < 7) {
            beg = cend;
            end = __shfl_sync(hm, offv, m + 2, 16);      // clamped: off[N]=E
            n = min(16, end - beg);
            u = __ldg(hu4 + (size_t)min(node + 1, N_NODES - 1) * 16 + hl);
            srcid = (hl < n) ? __ldg(&g_esrc[beg + hl]) : 0;
        }

        float4 acc = make_float4(0.f, 0.f, 0.f, 0.f);
        float denom = 0.f;
        int nq = (cn + 3) >> 2;                          // half-uniform

        for (int q = 0; q < nq; q++) {
            int k0 = 4 * q;
            float4 c0 = pr0, c1 = pr1, c2 = pr2, c3 = pr3;

            // cross-quad prefetch: next quad of this node, or next node's q0
            bool more = (q + 1 < nq);                    // half-uniform
            int psrc = more ? csrc : srcid;
            int pk   = more ? k0 + 4 : 0;
            int plim = more ? cn : ((m < 7) ? n : 0);
            int s0 = __shfl_sync(hm, psrc, min(pk + 0, 15), 16);
            int s1 = __shfl_sync(hm, psrc, min(pk + 1, 15), 16);
            int s2 = __shfl_sync(hm, psrc, min(pk + 2, 15), 16);
            int s3 = __shfl_sync(hm, psrc, min(pk + 3, 15), 16);
            if (pk + 0 < plim) pr0 = __ldg(hk4 + (size_t)s0 * 16 + hl);
            if (pk + 1 < plim) pr1 = __ldg(hk4 + (size_t)s1 * 16 + hl);
            if (pk + 2 < plim) pr2 = __ldg(hk4 + (size_t)s2 * 16 + hl);
            if (pk + 3 < plim) pr3 = __ldg(hk4 + (size_t)s3 * 16 + hl);

            // compute on current rows (stale pr values never pass the gates)
            float p0 = dot4(c0, cu), p1 = dot4(c1, cu);
            float p2 = dot4(c2, cu), p3 = dot4(c3, cu);
            #pragma unroll
            for (int o = 8; o; o >>= 1) {
                p0 += __shfl_xor_sync(hm, p0, o, 16);
                p1 += __shfl_xor_sync(hm, p1, o, 16);
                p2 += __shfl_xor_sync(hm, p2, o, 16);
                p3 += __shfl_xor_sync(hm, p3, o, 16);
            }
            { float e = __expf(p0);
              acc.x = fmaf(e, c0.x, acc.x); acc.y = fmaf(e, c0.y, acc.y);
              acc.z = fmaf(e, c0.z, acc.z); acc.w = fmaf(e, c0.w, acc.w); denom += e; }
            if (k0 + 1 < cn) { float e = __expf(p1);
              acc.x = fmaf(e, c1.x, acc.x); acc.y = fmaf(e, c1.y, acc.y);
              acc.z = fmaf(e, c1.z, acc.z); acc.w = fmaf(e, c1.w, acc.w); denom += e; }
            if (k0 + 2 < cn) { float e = __expf(p2);
              acc.x = fmaf(e, c2.x, acc.x); acc.y = fmaf(e, c2.y, acc.y);
              acc.z = fmaf(e, c2.z, acc.z); acc.w = fmaf(e, c2.w, acc.w); denom += e; }
            if (k0 + 3 < cn) { float e = __expf(p3);
              acc.x = fmaf(e, c3.x, acc.x); acc.y = fmaf(e, c3.y, acc.y);
              acc.z = fmaf(e, c3.z, acc.z); acc.w = fmaf(e, c3.w, acc.w); denom += e; }
        }
        if (nq == 0 && m < 7) {                          // deg-0 node: still prefetch
            int s0 = __shfl_sync(hm, srcid, 0, 16);
            int s1 = __shfl_sync(hm, srcid, 1, 16);
            int s2 = __shfl_sync(hm, srcid, 2, 16);
            int s3 = __shfl_sync(hm, srcid, 3, 16);
            if (0 < n) pr0 = __ldg(hk4 + (size_t)s0 * 16 + hl);
            if (1 < n) pr1 = __ldg(hk4 + (size_t)s1 * 16 + hl);
            if (2 < n) pr2 = __ldg(hk4 + (size_t)s2 * 16 + hl);
            if (3 < n) pr3 = __ldg(hk4 + (size_t)s3 * 16 + hl);
        }
        // deg>16 spillover blocks (rare): non-prefetched path
        for (int base2 = cbeg + 16; base2 < cend; base2 += 16) {
            int n2 = min(16, cend - base2);
            int sid2 = (hl < n2) ? __ldg(&g_esrc[base2 + hl]) : 0;
            process16(hm, hl, hk4, cu, sid2, n2, acc, denom);
        }

        float inv = (cend > cbeg) ? 1.f / denom : 0.f;   // deg==0 -> zero row
        int row = half * 8 + m;
        *(float4*)(stage + row * S_STRIDE + hl * 4) =
            make_float4(acc.x * inv, acc.y * inv, acc.z * inv, acc.w * inv);
    }
    __syncwarp();

    // ---- FC via mma.sync m16n8k8 tf32 (unchanged from R14 WIN) ----
    int g = lane >> 2, t = lane & 3;
    unsigned A0[8], A1[8], A2[8], A3[8];
    #pragma unroll
    for (int ks = 0; ks < 8; ks++) {
        A0[ks] = to_tf32(stage[ g      * S_STRIDE + ks * 8 + t    ]);
        A1[ks] = to_tf32(stage[(g + 8) * S_STRIDE + ks * 8 + t    ]);
        A2[ks] = to_tf32(stage[ g      * S_STRIDE + ks * 8 + t + 4]);
        A3[ks] = to_tf32(stage[(g + 8) * S_STRIDE + ks * 8 + t + 4]);
    }
    int n0 = nbase + g, n1 = n0 + 8;
    float2* out2 = (float2*)out;

    #pragma unroll 4
    for (int nt = 0; nt < 16; nt++) {
        float2 bb = __ldg((const float2*)b + nt * 4 + t);
        float c0 = bb.x, c1 = bb.y, c2 = bb.x, c3 = bb.y;
        #pragma unroll
        for (int ks = 0; ks < 8; ks++) {
            unsigned b0 = __float_as_uint(Wt_s[(ks * 8 + t    ) * W_STRIDE + nt * 8 + g]);
            unsigned b1 = __float_as_uint(Wt_s[(ks * 8 + t + 4) * W_STRIDE + nt * 8 + g]);
            asm volatile(
                "mma.sync.aligned.m16n8k8.row.col.f32.tf32.tf32.f32 "
                "{%0,%1,%2,%3}, {%4,%5,%6,%7}, {%8,%9}, {%0,%1,%2,%3};"
                : "+f"(c0), "+f"(c1), "+f"(c2), "+f"(c3)
                : "r"(A0[ks]), "r"(A1[ks]), "r"(A2[ks]), "r"(A3[ks]),
                  "r"(b0), "r"(b1));
        }
        c0 = fmaxf(c0, 0.f); c1 = fmaxf(c1, 0.f);
        c2 = fmaxf(c2, 0.f); c3 = fmaxf(c3, 0.f);
        if (n0 < N_NODES) out2[(size_t)n0 * 64 + nt * 4 + t] = make_float2(c0, c1);
        if (n1 < N_NODES) out2[(size_t)n1 * 64 + nt * 4 + t] = make_float2(c2, c3);
    }
}

// ---------------------------------------------------------------------------
// Inputs: hk[f32 N*64], hu[f32 N*64], W[f32 128*64], b[f32 128],
//         src[i32 E], dst[i32 E].  Output: f32 N*128.
// ---------------------------------------------------------------------------
extern "C" void kernel_launch(void* const* d_in, const int* in_sizes, int n_in,
                              void* d_out, int out_size) {
    const float* hk  = (const float*)d_in[0];
    const float* hu  = (const float*)d_in[1];
    const float* W   = (const float*)d_in[2];
    const float* b   = (const float*)d_in[3];
    const int*   src = (const int*)d_in[4];
    const int*   dst = (const int*)d_in[5];
    float* out = (float*)d_out;

    cudaFuncSetAttribute(attn_fc_kernel,
                         cudaFuncAttributeMaxDynamicSharedMemorySize, SMEM_BYTES);

    const int qblocks = (N_EDGES / 4 + 255) / 256;
    init_kernel<<<(N_NODES + 255) / 256, 256>>>(W);
    count_kernel<<<qblocks, 256>>>(dst);
    scan_fused_kernel<<<SCAN_BLOCKS, 256>>>();
    bin_kernel<<<qblocks, 256>>>(src, dst);
    attn_fc_kernel<<<(N_NODES + 127) / 128, 256, SMEM_BYTES>>>(hk, hu, b, out);
}